// round 16
// baseline (speedup 1.0000x reference)
#include <cuda_runtime.h>
#include <cuda_fp16.h>
#include <cstdint>

// ---------------------------------------------------------------- constants
#define BATCH   8192
#define IDIM    768
#define JDIM    768
#define GRID_G  5
#define KDIM    (IDIM * GRID_G)      // 3840

#define BM 128                        // CTA tile M
#define BN 96                         // CTA tile N  (512 tiles -> 86.5% balance)
#define BKH 64                        // fp16 K elems per chunk (128B rows)
#define NITER (KDIM / BKH)            // 60
#define MTILES (BATCH / BM)           // 64
#define NTILES_N (JDIM / BN)          // 8
#define NTILES (MTILES * NTILES_N)    // 512

#define A_TB (BM * 128)               // 16KB
#define B_TB (BN * 128)               // 12KB
#define STG 3
#define STAGE_B (A_TB + B_TB)         // 28KB
#define SMEM_DYN (STG * STAGE_B + 1024)
#define GRID_CTAS 296                 // 2 per SM x 148

// fp16 scratch (device globals -- no allocation allowed)
__device__ __half g_basis[(size_t)BATCH * KDIM];   // 63 MB   A[b][k], k = i*5+g
__device__ __half g_wt[(size_t)JDIM * KDIM];       // 5.9 MB  W^T[j][k]
__device__ float  g_bias[JDIM];
__device__ unsigned int g_ticket;

// ---------------------------------------------------------------- helpers
__device__ __forceinline__ uint32_t smem_u32(const void* p) {
    uint32_t a;
    asm("{ .reg .u64 t; cvta.to.shared.u64 t, %1; cvt.u32.u64 %0, t; }" : "=r"(a) : "l"(p));
    return a;
}
__device__ __forceinline__ void cp16(uint32_t dst, const void* src) {
    asm volatile("cp.async.cg.shared.global [%0], [%1], 16;\n" :: "r"(dst), "l"(src));
}
__device__ __forceinline__ void cp_commit() {
    asm volatile("cp.async.commit_group;\n" ::: "memory");
}
template <int N>
__device__ __forceinline__ void cp_wait() {
    asm volatile("cp.async.wait_group %0;\n" :: "n"(N) : "memory");
}
__device__ __forceinline__ void ldsm_x4(uint32_t& r0, uint32_t& r1, uint32_t& r2, uint32_t& r3,
                                        uint32_t addr) {
    asm volatile("ldmatrix.sync.aligned.m8n8.x4.shared.b16 {%0,%1,%2,%3}, [%4];"
                 : "=r"(r0), "=r"(r1), "=r"(r2), "=r"(r3) : "r"(addr));
}
__device__ __forceinline__ void mma16816(float c[4], const uint32_t a[4], const uint32_t b[2]) {
    asm volatile(
        "mma.sync.aligned.m16n8k16.row.col.f32.f16.f16.f32 "
        "{%0,%1,%2,%3}, {%4,%5,%6,%7}, {%8,%9}, {%0,%1,%2,%3};\n"
        : "+f"(c[0]), "+f"(c[1]), "+f"(c[2]), "+f"(c[3])
        : "r"(a[0]), "r"(a[1]), "r"(a[2]), "r"(a[3]), "r"(b[0]), "r"(b[1]));
}

// ---------------------------------------------------------------------------
// Kernel 1: pack W^T  g_wt[j][i*5+g] = fp16(coeffs[i,j,g] * scale[i,j])
// 32i x 32j smem-transpose tiles: coalesced reads AND coalesced writes.
// Also zeroes g_bias / ticket (runs first in stream order each replay).
// ---------------------------------------------------------------------------
#define PTI 32
#define PTJ 32
__global__ __launch_bounds__(256)
void pack_kernel(const float* __restrict__ coeffs,
                 const float* __restrict__ scale) {
    __shared__ float sc[PTI][PTJ * GRID_G];   // 20KB
    __shared__ float ss[PTI][PTJ];            // 4KB

    const int tid = threadIdx.x;
    {
        int gi = blockIdx.x * 256 + tid;
        if (gi < JDIM) g_bias[gi] = 0.f;
        if (gi == 0) g_ticket = 0u;
    }
    const int jb = JDIM / PTJ;                 // 24
    const int i0 = (blockIdx.x / jb) * PTI;
    const int j0 = (blockIdx.x % jb) * PTJ;

    #pragma unroll
    for (int r = 0; r < (PTI * PTJ * GRID_G) / 256; ++r) {   // 20 iters
        int idx = r * 256 + tid;
        int li = idx / (PTJ * GRID_G);
        int lc = idx - li * (PTJ * GRID_G);
        sc[li][lc] = __ldg(coeffs + ((size_t)(i0 + li) * JDIM + j0) * GRID_G + lc);
    }
    #pragma unroll
    for (int r = 0; r < (PTI * PTJ) / 256; ++r) {            // 4 iters
        int idx = r * 256 + tid;
        int li = idx / PTJ;
        int lj = idx - li * PTJ;
        ss[li][lj] = __ldg(scale + (size_t)(i0 + li) * JDIM + j0 + lj);
    }
    __syncthreads();

    for (int idx = tid; idx < PTJ * 20; idx += 256) {        // 640 segs
        int lj  = idx / 20;
        int seg = idx - lj * 20;
        union { __half h[8]; uint4 v; } o;
        #pragma unroll
        for (int e = 0; e < 8; ++e) {
            int el = seg * 8 + e;          // 0..159
            int li = el / GRID_G;
            int g  = el - li * GRID_G;
            o.h[e] = __float2half_rn(sc[li][lj * GRID_G + g] * ss[li][lj]);
        }
        *reinterpret_cast<uint4*>(g_wt + (size_t)(j0 + lj) * KDIM + i0 * GRID_G + seg * 8) = o.v;
    }
}

// ---------------------------------------------------------------------------
// Kernel 2: bias[j] += sum over this block's 32-row i-chunk of shift[i,j]
// ---------------------------------------------------------------------------
__global__ void bias_kernel(const float* __restrict__ shift) {
    const int i0 = blockIdx.x * 32;
    #pragma unroll
    for (int jj = 0; jj < 3; ++jj) {
        const int j = jj * 256 + threadIdx.x;
        float s = 0.f;
        #pragma unroll 8
        for (int ii = 0; ii < 32; ++ii)
            s += shift[(size_t)(i0 + ii) * JDIM + j];
        atomicAdd(&g_bias[j], s);
    }
}

// ---------------------------------------------------------------------------
// Kernel 3: basis (fp16), 8 i-values per thread, 5 x 16B vector stores.
//   t=tanh(x); p=e^{-5t^2}; u=e^{5t}; v=1/u
//   exp(-5(t - grid_g)^2) = p * c_g * u^{2*grid_g};  grid = {-1,-.5,0,.5,1}
// ---------------------------------------------------------------------------
__global__ void basis_kernel(const float* __restrict__ x) {
    int idx = blockIdx.x * blockDim.x + threadIdx.x;   // over BATCH*IDIM/8
    if (idx >= BATCH * IDIM / 8) return;
    const float4 x0 = *reinterpret_cast<const float4*>(x + (size_t)idx * 8);
    const float4 x1 = *reinterpret_cast<const float4*>(x + (size_t)idx * 8 + 4);
    float xs[8] = {x0.x, x0.y, x0.z, x0.w, x1.x, x1.y, x1.z, x1.w};

    union { __half h[40]; uint4 v[5]; } out;
    const float L5 = 7.21347520444482f;                 // 5*log2(e)
    const float c1 = 0.2865047968601901f;               // e^-1.25
    const float c2 = 0.006737946999085467f;             // e^-5
    #pragma unroll
    for (int e = 0; e < 8; ++e) {
        float t, u, p, v;
        asm("tanh.approx.f32 %0, %1;" : "=f"(t) : "f"(xs[e]));
        float a = L5 * t;
        asm("ex2.approx.ftz.f32 %0, %1;" : "=f"(u) : "f"(a));
        float na = -a * t;                               // -5*log2(e)*t^2
        asm("ex2.approx.ftz.f32 %0, %1;" : "=f"(p) : "f"(na));
        asm("rcp.approx.ftz.f32 %0, %1;" : "=f"(v) : "f"(u));
        out.h[e * 5 + 0] = __float2half_rn(p * c2 * v * v);
        out.h[e * 5 + 1] = __float2half_rn(p * c1 * v);
        out.h[e * 5 + 2] = __float2half_rn(p);
        out.h[e * 5 + 3] = __float2half_rn(p * c1 * u);
        out.h[e * 5 + 4] = __float2half_rn(p * c2 * u * u);
    }
    uint4* dst = reinterpret_cast<uint4*>(g_basis + (size_t)idx * 40);
    #pragma unroll
    for (int q = 0; q < 5; ++q) dst[q] = out.v[q];
}

// ---------------------------------------------------------------------------
// Kernel 4: GEMM  C[b,j] = sum_k A[b,k] W^T[j,k] + bias[j]
// 128x96 CTA tiles (512 tiles: 86.5% ticket balance), 8 warps as 4m x 2n
// (32x48 warp tiles), 3-stage cp.async, 1 sync per K chunk.
// ---------------------------------------------------------------------------
__global__ __launch_bounds__(256, 2)
void gemm_kernel(float* __restrict__ C) {
    extern __shared__ char dsmem[];
    __shared__ unsigned s_tile;
    const uint32_t sbase = (smem_u32(dsmem) + 1023u) & ~1023u;

    const int tid  = threadIdx.x;
    const int lane = tid & 31;
    const int wid  = tid >> 5;            // 0..7
    const int wm   = (wid & 3) * 32;      // 4 m-rows of warps
    const int wn   = (wid >> 2) * 48;     // 2 n-cols of warps

    // staging indices
    const int srow = tid >> 3;                       // 0..31
    const int sseg = (tid & 7) * 16;                 // byte col 0..112
    const uint32_t swcol = (uint32_t)(sseg ^ ((srow & 7) << 4));
    const int scol_h = sseg >> 1;                    // half offset within row

    // ldmatrix lane addressing (verified maps)
    const int arow0 = wm + (lane & 7) + 8 * ((lane >> 3) & 1);    // + mt*16
    const uint32_t axor = (uint32_t)((lane & 7) << 4);
    const uint32_t acol = (uint32_t)(16 * (lane >> 4));           // + 32*ks
    const int brow0 = wn + (lane & 7) + 8 * (lane >> 4);          // + jg*16
    const uint32_t bcol = (uint32_t)(16 * ((lane >> 3) & 1));     // + 32*ks

    for (;;) {
        if (tid == 0) s_tile = atomicAdd(&g_ticket, 1u);
        __syncthreads();                 // also guards smem reuse across tiles
        const unsigned t = s_tile;
        if (t >= NTILES) break;
        const int m0 = (int)(t / NTILES_N) * BM;
        const int n0 = (int)(t % NTILES_N) * BN;

        const __half* aglob = g_basis + (size_t)(m0 + srow) * KDIM + scol_h;
        const __half* bglob = g_wt   + (size_t)(n0 + srow) * KDIM + scol_h;

        float acc[2][6][4];
        #pragma unroll
        for (int mt = 0; mt < 2; ++mt)
            #pragma unroll
            for (int nt = 0; nt < 6; ++nt)
                #pragma unroll
                for (int r = 0; r < 4; ++r) acc[mt][nt][r] = 0.f;

        // prologue: chunks 0 and 1
        #pragma unroll
        for (int pc = 0; pc < 2; ++pc) {
            const uint32_t sb = sbase + pc * STAGE_B;
            #pragma unroll
            for (int q = 0; q < 4; ++q)
                cp16(sb + (srow + 32 * q) * 128 + swcol, aglob + pc * BKH + (size_t)(32 * q) * KDIM);
            #pragma unroll
            for (int q = 0; q < 3; ++q)
                cp16(sb + A_TB + (srow + 32 * q) * 128 + swcol, bglob + pc * BKH + (size_t)(32 * q) * KDIM);
            cp_commit();
        }

        int slot = 0, pslot = 2;
        for (int kt = 0; kt < NITER; ++kt) {
            cp_wait<1>();
            __syncthreads();

            // prefetch chunk kt+2 into pslot
            if (kt + 2 < NITER) {
                const int kh = (kt + 2) * BKH;
                const uint32_t sb = sbase + pslot * STAGE_B;
                #pragma unroll
                for (int q = 0; q < 4; ++q)
                    cp16(sb + (srow + 32 * q) * 128 + swcol, aglob + kh + (size_t)(32 * q) * KDIM);
                #pragma unroll
                for (int q = 0; q < 3; ++q)
                    cp16(sb + A_TB + (srow + 32 * q) * 128 + swcol, bglob + kh + (size_t)(32 * q) * KDIM);
            }
            cp_commit();   // always: keeps exactly 2 groups pending

            const uint32_t abase = sbase + slot * STAGE_B;
            const uint32_t bbase = abase + A_TB;

            #pragma unroll
            for (int ks = 0; ks < 4; ++ks) {
                uint32_t af[2][4];
                #pragma unroll
                for (int mt = 0; mt < 2; ++mt) {
                    uint32_t addr = abase + (uint32_t)(arow0 + mt * 16) * 128
                                  + ((acol + 32 * ks) ^ axor);
                    ldsm_x4(af[mt][0], af[mt][1], af[mt][2], af[mt][3], addr);
                }
                uint32_t bf[6][2];
                #pragma unroll
                for (int jg = 0; jg < 3; ++jg) {
                    uint32_t addr = bbase + (uint32_t)(brow0 + jg * 16) * 128
                                  + ((bcol + 32 * ks) ^ axor);
                    ldsm_x4(bf[2 * jg][0], bf[2 * jg][1], bf[2 * jg + 1][0], bf[2 * jg + 1][1], addr);
                }
                #pragma unroll
                for (int mt = 0; mt < 2; ++mt)
                    #pragma unroll
                    for (int nt = 0; nt < 6; ++nt)
                        mma16816(acc[mt][nt], af[mt], bf[nt]);
            }

            slot = (slot + 1 == STG) ? 0 : slot + 1;
            pslot = (pslot + 1 == STG) ? 0 : pslot + 1;
        }

        // epilogue: add bias, write fp32 out
        #pragma unroll
        for (int mt = 0; mt < 2; ++mt) {
            const int r0 = m0 + wm + mt * 16 + (lane >> 2);
            #pragma unroll
            for (int nt = 0; nt < 6; ++nt) {
                const int c0 = n0 + wn + nt * 8 + 2 * (lane & 3);
                const float bv0 = g_bias[c0];
                const float bv1 = g_bias[c0 + 1];
                float2 v0 = make_float2(acc[mt][nt][0] + bv0, acc[mt][nt][1] + bv1);
                float2 v1 = make_float2(acc[mt][nt][2] + bv0, acc[mt][nt][3] + bv1);
                *reinterpret_cast<float2*>(C + (size_t)r0 * JDIM + c0) = v0;
                *reinterpret_cast<float2*>(C + (size_t)(r0 + 8) * JDIM + c0) = v1;
            }
        }
    }
}

// ---------------------------------------------------------------------------
extern "C" void kernel_launch(void* const* d_in, const int* in_sizes, int n_in,
                              void* d_out, int out_size) {
    const float* x      = (const float*)d_in[0];
    const float* coeffs = (const float*)d_in[1];
    const float* scale  = (const float*)d_in[2];
    const float* shift  = (const float*)d_in[3];
    float* out = (float*)d_out;

    pack_kernel<<<(IDIM / PTI) * (JDIM / PTJ), 256>>>(coeffs, scale);
    bias_kernel<<<IDIM / 32, 256>>>(shift);
    basis_kernel<<<(BATCH * IDIM / 8 + 255) / 256, 256>>>(x);

    cudaFuncSetAttribute(gemm_kernel, cudaFuncAttributeMaxDynamicSharedMemorySize, SMEM_DYN);
    gemm_kernel<<<GRID_CTAS, 256, SMEM_DYN>>>(out);
}